// round 8
// baseline (speedup 1.0000x reference)
#include <cuda_runtime.h>
#include <cuda_bf16.h>
#include <mma.h>

using namespace nvcuda;

// Problem constants (fixed by the dataset)
#define NN 100000
#define EE 1600000
#define FF 128
#define NC 40
#define SCAN_B 512
#define SCAN_NB ((NN + SCAN_B - 1) / SCAN_B)   // 196

// Scratch (device globals; no allocation)
__device__ float g_bufA[NN * FF];
__device__ float g_bufB[NN * FF];
__device__ float g_bufC[NN * FF];
__device__ int   g_deg[NN];
__device__ int   g_excl[NN];
__device__ int   g_btot[SCAN_NB];
__device__ int   g_off[NN + 1];
__device__ int   g_cur[NN];
__device__ int2  g_se[EE];       // packed {src, bitcast(ea)} sorted by dst

// Packed hi/lo bf16 split of a float pair (1 conversion instr per 2 elems per array)
__device__ __forceinline__ void split_pair(float a, float b, unsigned& h, unsigned& l) {
    __nv_bfloat162 hh = __floats2bfloat162_rn(a, b);
    float2 hf = __bfloat1622float2(hh);
    __nv_bfloat162 ll = __floats2bfloat162_rn(a - hf.x, b - hf.y);
    h = *(unsigned*)&hh;
    l = *(unsigned*)&ll;
}

// ---------------------------------------------------------------------------
// Sort pipeline: counting sort of edges by dst
// ---------------------------------------------------------------------------
__global__ void zero_int(int* p, int n) {
    int i = blockIdx.x * blockDim.x + threadIdx.x;
    if (i < n) p[i] = 0;
}

__global__ void count_deg(const int* __restrict__ ei, int* __restrict__ deg, int E) {
    int e = blockIdx.x * blockDim.x + threadIdx.x;
    if (e < E) atomicAdd(&deg[ei[E + e]], 1);
}

__global__ void scan1(const int* __restrict__ deg, int* __restrict__ excl,
                      int* __restrict__ btot, int n) {
    __shared__ int sm[SCAN_B];
    int i = blockIdx.x * SCAN_B + threadIdx.x;
    int v = (i < n) ? deg[i] : 0;
    sm[threadIdx.x] = v;
    __syncthreads();
    for (int off = 1; off < SCAN_B; off <<= 1) {
        int t = (threadIdx.x >= off) ? sm[threadIdx.x - off] : 0;
        __syncthreads();
        sm[threadIdx.x] += t;
        __syncthreads();
    }
    int incl = sm[threadIdx.x];
    if (i < n) excl[i] = incl - v;
    if (threadIdx.x == SCAN_B - 1) btot[blockIdx.x] = incl;
}

__global__ void scan2(int* __restrict__ btot, int nb) {
    __shared__ int sm[256];
    int t = threadIdx.x;
    int v = (t < nb) ? btot[t] : 0;
    sm[t] = v;
    __syncthreads();
    for (int off = 1; off < 256; off <<= 1) {
        int u = (t >= off) ? sm[t - off] : 0;
        __syncthreads();
        sm[t] += u;
        __syncthreads();
    }
    if (t < nb) btot[t] = sm[t] - v;
}

__global__ void scan3(const int* __restrict__ excl, const int* __restrict__ btot,
                      int* __restrict__ off, int* __restrict__ cur, int n, int E) {
    int i = blockIdx.x * SCAN_B + threadIdx.x;
    if (i < n) {
        int o = excl[i] + btot[blockIdx.x];
        off[i] = o;
        cur[i] = o;
    }
    if (i == n) off[n] = E;
}

__global__ void scatter_edges(const int* __restrict__ ei, const float* __restrict__ ea,
                              int* __restrict__ cur, int2* __restrict__ se, int E) {
    int e = blockIdx.x * blockDim.x + threadIdx.x;
    if (e < E) {
        int src = ei[e];
        int dst = ei[E + e];
        int p = atomicAdd(&cur[dst], 1);
        se[p] = make_int2(src, __float_as_int(ea[e]));
    }
}

// ---------------------------------------------------------------------------
// Pull aggregation, no atomics: warp-per-node over CSR segment.
// 3-stage software pipeline, chunk=4: edge records prefetched 2 chunks ahead,
// x rows 1 chunk ahead -> MLP ~4-8 instead of 1-2 (latency-bound before).
// aggr[n] = (1+eps)*x[n] + sum_{e in seg(n)} relu(x[src_e] + ea_e*We + be)
// ---------------------------------------------------------------------------
__global__ void __launch_bounds__(256) aggregate(
    const float4* __restrict__ x,          // [N,32] float4 view
    const int2* __restrict__ se,           // sorted {src, ea}
    const int* __restrict__ off,           // [N+1]
    const float* __restrict__ eps,
    const float* __restrict__ We,          // [128]
    const float* __restrict__ be,          // [128]
    float4* __restrict__ aggr,             // [N,32] float4 view
    int N)
{
    const int lane = threadIdx.x & 31;
    const int node = (blockIdx.x * blockDim.x + threadIdx.x) >> 5;
    if (node >= N) return;

    const float4 we4 = ((const float4*)We)[lane];
    const float4 be4 = ((const float4*)be)[lane];

    int start = off[node];
    int end = off[node + 1];
    int len = end - start;
    const int2* sp = se + start;

    float s = 1.0f + *eps;
    float4 acc = x[(size_t)node * 32 + lane];
    acc.x *= s; acc.y *= s; acc.z *= s; acc.w *= s;

    if (len > 0) {
        int2 pA[4], pB[4];
        float4 xq[4];
        // prologue: records chunk0 -> pA; x(chunk0) -> xq; records chunk1 -> pB
#pragma unroll
        for (int k = 0; k < 4; k++)
            pA[k] = (k < len) ? __ldg(&sp[k]) : make_int2(0, 0);
#pragma unroll
        for (int k = 0; k < 4; k++)
            xq[k] = x[(size_t)pA[k].x * 32 + lane];
#pragma unroll
        for (int k = 0; k < 4; k++)
            pB[k] = (4 + k < len) ? __ldg(&sp[4 + k]) : make_int2(0, 0);

        for (int c = 0; c * 4 < len; c++) {
            bool more = (c + 1) * 4 < len;
            // issue x loads for chunk c+1 (records already resident in pB)
            float4 xn[4];
            if (more) {
#pragma unroll
                for (int k = 0; k < 4; k++)
                    xn[k] = x[(size_t)pB[k].x * 32 + lane];
            }
            // issue record loads for chunk c+2
            int2 pC[4];
#pragma unroll
            for (int k = 0; k < 4; k++) {
                int idx = (c + 2) * 4 + k;
                pC[k] = (idx < len) ? __ldg(&sp[idx]) : make_int2(0, 0);
            }
            // accumulate chunk c
#pragma unroll
            for (int k = 0; k < 4; k++) {
                if (c * 4 + k < len) {
                    float a = __int_as_float(pA[k].y);
                    float4 xv = xq[k];
                    acc.x += fmaxf(fmaf(a, we4.x, xv.x + be4.x), 0.0f);
                    acc.y += fmaxf(fmaf(a, we4.y, xv.y + be4.y), 0.0f);
                    acc.z += fmaxf(fmaf(a, we4.z, xv.z + be4.z), 0.0f);
                    acc.w += fmaxf(fmaf(a, we4.w, xv.w + be4.w), 0.0f);
                }
            }
            // rotate pipeline
#pragma unroll
            for (int k = 0; k < 4; k++) {
                pA[k] = pB[k];
                pB[k] = pC[k];
                if (more) xq[k] = xn[k];
            }
        }
    }
    aggr[(size_t)node * 32 + lane] = acc;
}

// ---------------------------------------------------------------------------
// Tensor-core GEMM, bf16 hi/lo split (3 MMAs, ~2^-17 product error):
//   C[M,128] = act(A[M,128] @ W[128,128] + bias)
// CTA: 128m x 128n, BK=32 chunks, 8 warps (4m x 2n), wmma m16n16k16 bf16.
// Split conversion: packed bf16x2 + 64-bit smem stores (was the bottleneck).
// ---------------------------------------------------------------------------
template <bool RELU>
__global__ void __launch_bounds__(256) gemm_bf(
    const float* __restrict__ A, const float* __restrict__ W,
    const float* __restrict__ bias, float* __restrict__ C, int M)
{
    __shared__ __nv_bfloat16 sAh[128][40];   // [m][k], pad 40
    __shared__ __nv_bfloat16 sAl[128][40];
    __shared__ __nv_bfloat16 sWh[32][136];   // [k][n], pad 136
    __shared__ __nv_bfloat16 sWl[32][136];

    const int tid = threadIdx.x;
    const int wid = tid >> 5;
    const int lane = tid & 31;
    const int r0 = blockIdx.x * 128;
    const int wm = (wid & 3) * 32;     // warp m-offset
    const int wn = (wid >> 2) * 64;    // warp n-offset

    wmma::fragment<wmma::accumulator, 16, 16, 16, float> acc[2][4];
#pragma unroll
    for (int i = 0; i < 2; i++)
#pragma unroll
        for (int j = 0; j < 4; j++) wmma::fill_fragment(acc[i][j], 0.0f);

    for (int kb = 0; kb < 128; kb += 32) {
        // A chunk 128x32: 1024 float4 over 256 threads, packed split on store
#pragma unroll
        for (int i = 0; i < 4; i++) {
            int idx = tid + i * 256;
            int m = idx >> 3, k4 = idx & 7;
            int gr = r0 + m;
            if (gr >= M) gr = r0;
            float4 v = *(const float4*)(A + (size_t)gr * 128 + kb + k4 * 4);
            unsigned h0, l0, h1, l1;
            split_pair(v.x, v.y, h0, l0);
            split_pair(v.z, v.w, h1, l1);
            *(uint2*)&sAh[m][k4 * 4] = make_uint2(h0, h1);
            *(uint2*)&sAl[m][k4 * 4] = make_uint2(l0, l1);
        }
        // W chunk 32x128
#pragma unroll
        for (int i = 0; i < 4; i++) {
            int idx = tid + i * 256;
            int k = idx >> 5, n4 = idx & 31;
            float4 v = *(const float4*)(W + (size_t)(kb + k) * 128 + n4 * 4);
            unsigned h0, l0, h1, l1;
            split_pair(v.x, v.y, h0, l0);
            split_pair(v.z, v.w, h1, l1);
            *(uint2*)&sWh[k][n4 * 4] = make_uint2(h0, h1);
            *(uint2*)&sWl[k][n4 * 4] = make_uint2(l0, l1);
        }
        __syncthreads();

#pragma unroll
        for (int ks = 0; ks < 2; ks++) {
            wmma::fragment<wmma::matrix_a, 16, 16, 16, __nv_bfloat16, wmma::row_major> ah[2], al[2];
#pragma unroll
            for (int im = 0; im < 2; im++) {
                wmma::load_matrix_sync(ah[im], &sAh[wm + im * 16][ks * 16], 40);
                wmma::load_matrix_sync(al[im], &sAl[wm + im * 16][ks * 16], 40);
            }
#pragma unroll
            for (int in = 0; in < 4; in++) {
                wmma::fragment<wmma::matrix_b, 16, 16, 16, __nv_bfloat16, wmma::row_major> bh, bl;
                wmma::load_matrix_sync(bh, &sWh[ks * 16][wn + in * 16], 136);
                wmma::load_matrix_sync(bl, &sWl[ks * 16][wn + in * 16], 136);
#pragma unroll
                for (int im = 0; im < 2; im++) {
                    wmma::mma_sync(acc[im][in], ah[im], bh, acc[im][in]);
                    wmma::mma_sync(acc[im][in], ah[im], bl, acc[im][in]);
                    wmma::mma_sync(acc[im][in], al[im], bh, acc[im][in]);
                }
            }
        }
        __syncthreads();
    }

    // Epilogue: alias the A-tile smem as per-warp fp32 scratch (16x16, ldm 20)
    float* scratch = (float*)&sAh[0][0] + wid * 320;   // 8 warps * 320 floats = 10KB

#pragma unroll
    for (int im = 0; im < 2; im++) {
#pragma unroll
        for (int in = 0; in < 4; in++) {
            wmma::store_matrix_sync(scratch, acc[im][in], 20, wmma::mem_row_major);
            __syncwarp();
            int row = lane >> 2;    // 0..7
            int c4 = lane & 3;      // 0..3
            int ncol = wn + in * 16 + c4 * 4;
            float4 bb = *(const float4*)(bias + ncol);
#pragma unroll
            for (int h = 0; h < 2; h++) {
                int r = row + h * 8;
                int gr = r0 + wm + im * 16 + r;
                if (gr < M) {
                    float4 v = *(float4*)&scratch[r * 20 + c4 * 4];
                    v.x += bb.x; v.y += bb.y; v.z += bb.z; v.w += bb.w;
                    if (RELU) {
                        v.x = fmaxf(v.x, 0.f); v.y = fmaxf(v.y, 0.f);
                        v.z = fmaxf(v.z, 0.f); v.w = fmaxf(v.w, 0.f);
                    }
                    *(float4*)(C + (size_t)gr * 128 + ncol) = v;
                }
            }
            __syncwarp();
        }
    }
}

// ---------------------------------------------------------------------------
// out[n, :] = log_softmax(H[n, :] @ Wl + bl)
// ---------------------------------------------------------------------------
__global__ void __launch_bounds__(256) classify_lsm(
    const float* __restrict__ H, const float* __restrict__ Wl,
    const float* __restrict__ bl, float* __restrict__ out, int M)
{
    __shared__ float sW[128 * NC];
    __shared__ float sb[NC];
    __shared__ float sh[32 * 129];
    __shared__ float sl[32 * NC];

    const int tid = threadIdx.x;
    const int r0 = blockIdx.x * 32;

    for (int i = tid; i < 128 * NC; i += 256) sW[i] = Wl[i];
    if (tid < NC) sb[tid] = bl[tid];
    for (int i = tid; i < 32 * 128; i += 256) {
        int row = i >> 7, col = i & 127;
        int gr = r0 + row;
        sh[row * 129 + col] = (gr < M) ? H[(size_t)gr * 128 + col] : 0.0f;
    }
    __syncthreads();

#pragma unroll
    for (int t = 0; t < 5; t++) {
        int idx = tid + t * 256;
        int row = idx / NC, col = idx % NC;
        float acc = sb[col];
#pragma unroll 8
        for (int k = 0; k < 128; k++)
            acc = fmaf(sh[row * 129 + k], sW[k * NC + col], acc);
        sl[row * NC + col] = acc;
    }
    __syncthreads();

    if (tid < 32) {
        int row = tid;
        int gr = r0 + row;
        if (gr < M) {
            float mx = -1e30f;
            for (int c = 0; c < NC; c++) mx = fmaxf(mx, sl[row * NC + c]);
            float sum = 0.0f;
            for (int c = 0; c < NC; c++) sum += expf(sl[row * NC + c] - mx);
            float lse = mx + logf(sum);
            for (int c = 0; c < NC; c++)
                out[(size_t)gr * NC + c] = sl[row * NC + c] - lse;
        }
    }
}

// ---------------------------------------------------------------------------
extern "C" void kernel_launch(void* const* d_in, const int* in_sizes, int n_in,
                              void* d_out, int out_size)
{
    const float* x    = (const float*)d_in[0];
    const int*   ei   = (const int*)d_in[1];      // int32 (JAX x64 disabled)
    const float* ea   = (const float*)d_in[2];
    const float* eps1 = (const float*)d_in[3];
    const float* We1  = (const float*)d_in[4];
    const float* be1  = (const float*)d_in[5];
    const float* W11  = (const float*)d_in[6];
    const float* b11  = (const float*)d_in[7];
    const float* W12  = (const float*)d_in[8];
    const float* b12  = (const float*)d_in[9];
    const float* eps2 = (const float*)d_in[10];
    const float* We2  = (const float*)d_in[11];
    const float* be2  = (const float*)d_in[12];
    const float* W21  = (const float*)d_in[13];
    const float* b21  = (const float*)d_in[14];
    const float* W22  = (const float*)d_in[15];
    const float* b22  = (const float*)d_in[16];
    const float* Wl   = (const float*)d_in[17];
    const float* bl   = (const float*)d_in[18];
    float* out = (float*)d_out;

    const int N = NN;
    const int E = in_sizes[2];

    float *A, *B, *C;
    int *deg, *excl, *btot, *off, *cur;
    int2 *se;
    cudaGetSymbolAddress((void**)&A, g_bufA);
    cudaGetSymbolAddress((void**)&B, g_bufB);
    cudaGetSymbolAddress((void**)&C, g_bufC);
    cudaGetSymbolAddress((void**)&deg, g_deg);
    cudaGetSymbolAddress((void**)&excl, g_excl);
    cudaGetSymbolAddress((void**)&btot, g_btot);
    cudaGetSymbolAddress((void**)&off, g_off);
    cudaGetSymbolAddress((void**)&cur, g_cur);
    cudaGetSymbolAddress((void**)&se, g_se);

    const int eb = (E + 255) / 256;
    const int nb = (N + 255) / 256;
    const int gemm_blocks = (N + 127) / 128;
    const int cls_blocks = (N + 31) / 32;
    const int agg_blocks = (N * 32 + 255) / 256;   // warp per node

    // ---- One-time counting sort of edges by dst ----
    zero_int<<<nb, 256>>>(deg, N);
    count_deg<<<eb, 256>>>(ei, deg, E);
    scan1<<<SCAN_NB, SCAN_B>>>(deg, excl, btot, N);
    scan2<<<1, 256>>>(btot, SCAN_NB);
    scan3<<<SCAN_NB, SCAN_B>>>(excl, btot, off, cur, N, E);
    scatter_edges<<<eb, 256>>>(ei, ea, cur, se, E);

    // ---- Layer 1 ----
    aggregate<<<agg_blocks, 256>>>((const float4*)x, se, off, eps1, We1, be1,
                                   (float4*)A, N);
    gemm_bf<true><<<gemm_blocks, 256>>>(A, W11, b11, B, N);
    gemm_bf<true><<<gemm_blocks, 256>>>(B, W12, b12, C, N);   // outer relu fused

    // ---- Layer 2 ----
    aggregate<<<agg_blocks, 256>>>((const float4*)C, se, off, eps2, We2, be2,
                                   (float4*)B, N);
    gemm_bf<true><<<gemm_blocks, 256>>>(B, W21, b21, A, N);
    gemm_bf<true><<<gemm_blocks, 256>>>(A, W22, b22, B, N);   // outer relu fused

    // ---- Classifier + log_softmax ----
    classify_lsm<<<cls_blocks, 256>>>(B, Wl, bl, out, N);
}

// round 10
// speedup vs baseline: 1.1139x; 1.1139x over previous
#include <cuda_runtime.h>
#include <cuda_bf16.h>
#include <mma.h>

using namespace nvcuda;

// Problem constants (fixed by the dataset)
#define NN 100000
#define EE 1600000
#define FF 128
#define NC 40
#define SCAN_B 512
#define SCAN_NB ((NN + SCAN_B - 1) / SCAN_B)   // 196

// Scratch (device globals; no allocation)
__device__ float g_bufA[NN * FF];
__device__ float g_bufB[NN * FF];
__device__ float g_bufC[NN * FF];
__device__ int   g_deg[NN];
__device__ int   g_excl[NN];
__device__ int   g_btot[SCAN_NB];
__device__ int   g_off[NN + 1];
__device__ int   g_cur[NN];
__device__ int2  g_se[EE];       // packed {src, bitcast(ea)} sorted by dst

// Packed hi/lo bf16 split of a float pair (1 conversion instr per 2 elems per array)
__device__ __forceinline__ void split_pair(float a, float b, unsigned& h, unsigned& l) {
    __nv_bfloat162 hh = __floats2bfloat162_rn(a, b);
    float2 hf = __bfloat1622float2(hh);
    __nv_bfloat162 ll = __floats2bfloat162_rn(a - hf.x, b - hf.y);
    h = *(unsigned*)&hh;
    l = *(unsigned*)&ll;
}

// ---------------------------------------------------------------------------
// Sort pipeline: counting sort of edges by dst
// ---------------------------------------------------------------------------
__global__ void zero_int(int* p, int n) {
    int i = blockIdx.x * blockDim.x + threadIdx.x;
    if (i < n) p[i] = 0;
}

__global__ void count_deg(const int* __restrict__ ei, int* __restrict__ deg, int E) {
    int e = blockIdx.x * blockDim.x + threadIdx.x;
    if (e < E) atomicAdd(&deg[ei[E + e]], 1);
}

__global__ void scan1(const int* __restrict__ deg, int* __restrict__ excl,
                      int* __restrict__ btot, int n) {
    __shared__ int sm[SCAN_B];
    int i = blockIdx.x * SCAN_B + threadIdx.x;
    int v = (i < n) ? deg[i] : 0;
    sm[threadIdx.x] = v;
    __syncthreads();
    for (int off = 1; off < SCAN_B; off <<= 1) {
        int t = (threadIdx.x >= off) ? sm[threadIdx.x - off] : 0;
        __syncthreads();
        sm[threadIdx.x] += t;
        __syncthreads();
    }
    int incl = sm[threadIdx.x];
    if (i < n) excl[i] = incl - v;
    if (threadIdx.x == SCAN_B - 1) btot[blockIdx.x] = incl;
}

__global__ void scan2(int* __restrict__ btot, int nb) {
    __shared__ int sm[256];
    int t = threadIdx.x;
    int v = (t < nb) ? btot[t] : 0;
    sm[t] = v;
    __syncthreads();
    for (int off = 1; off < 256; off <<= 1) {
        int u = (t >= off) ? sm[t - off] : 0;
        __syncthreads();
        sm[t] += u;
        __syncthreads();
    }
    if (t < nb) btot[t] = sm[t] - v;
}

__global__ void scan3(const int* __restrict__ excl, const int* __restrict__ btot,
                      int* __restrict__ off, int* __restrict__ cur, int n, int E) {
    int i = blockIdx.x * SCAN_B + threadIdx.x;
    if (i < n) {
        int o = excl[i] + btot[blockIdx.x];
        off[i] = o;
        cur[i] = o;
    }
    if (i == n) off[n] = E;
}

__global__ void scatter_edges(const int* __restrict__ ei, const float* __restrict__ ea,
                              int* __restrict__ cur, int2* __restrict__ se, int E) {
    int e = blockIdx.x * blockDim.x + threadIdx.x;
    if (e < E) {
        int src = ei[e];
        int dst = ei[E + e];
        int p = atomicAdd(&cur[dst], 1);
        se[p] = make_int2(src, __float_as_int(ea[e]));
    }
}

// ---------------------------------------------------------------------------
// Pull aggregation, no atomics: warp-per-node over CSR segment.
// (Round-6 proven version: simple 1-deep record prefetch; inter-warp
//  parallelism supplies the MLP — deeper intra-warp pipelining regressed.)
// aggr[n] = (1+eps)*x[n] + sum_{e in seg(n)} relu(x[src_e] + ea_e*We + be)
// ---------------------------------------------------------------------------
__global__ void __launch_bounds__(256) aggregate(
    const float4* __restrict__ x,          // [N,32] float4 view
    const int2* __restrict__ se,           // sorted {src, ea}
    const int* __restrict__ off,           // [N+1]
    const float* __restrict__ eps,
    const float* __restrict__ We,          // [128]
    const float* __restrict__ be,          // [128]
    float4* __restrict__ aggr,             // [N,32] float4 view
    int N)
{
    const int lane = threadIdx.x & 31;
    const int node = (blockIdx.x * blockDim.x + threadIdx.x) >> 5;
    if (node >= N) return;

    const float4 we4 = ((const float4*)We)[lane];
    const float4 be4 = ((const float4*)be)[lane];

    int start = off[node];
    int end = off[node + 1];

    float s = 1.0f + *eps;
    float4 acc = x[(size_t)node * 32 + lane];
    acc.x *= s; acc.y *= s; acc.z *= s; acc.w *= s;

    int2 p;
    if (start < end) p = __ldg(&se[start]);
    for (int e = start; e < end; e++) {
        int src = p.x;
        float a = __int_as_float(p.y);
        if (e + 1 < end) p = __ldg(&se[e + 1]);
        float4 xv = x[(size_t)src * 32 + lane];
        acc.x += fmaxf(fmaf(a, we4.x, xv.x + be4.x), 0.0f);
        acc.y += fmaxf(fmaf(a, we4.y, xv.y + be4.y), 0.0f);
        acc.z += fmaxf(fmaf(a, we4.z, xv.z + be4.z), 0.0f);
        acc.w += fmaxf(fmaf(a, we4.w, xv.w + be4.w), 0.0f);
    }
    aggr[(size_t)node * 32 + lane] = acc;
}

// ---------------------------------------------------------------------------
// Tensor-core GEMM, bf16 hi/lo split (3 MMAs, ~2^-17 product error):
//   C[M,128] = act(A[M,128] @ W[128,128] + bias)
// CTA: 128m x 128n, BK=32 chunks, 8 warps (4m x 2n), wmma m16n16k16 bf16.
// Split conversion: packed bf16x2 + 64-bit smem stores.
// ---------------------------------------------------------------------------
template <bool RELU>
__global__ void __launch_bounds__(256) gemm_bf(
    const float* __restrict__ A, const float* __restrict__ W,
    const float* __restrict__ bias, float* __restrict__ C, int M)
{
    __shared__ __nv_bfloat16 sAh[128][40];   // [m][k], pad 40
    __shared__ __nv_bfloat16 sAl[128][40];
    __shared__ __nv_bfloat16 sWh[32][136];   // [k][n], pad 136
    __shared__ __nv_bfloat16 sWl[32][136];

    const int tid = threadIdx.x;
    const int wid = tid >> 5;
    const int lane = tid & 31;
    const int r0 = blockIdx.x * 128;
    const int wm = (wid & 3) * 32;     // warp m-offset
    const int wn = (wid >> 2) * 64;    // warp n-offset

    wmma::fragment<wmma::accumulator, 16, 16, 16, float> acc[2][4];
#pragma unroll
    for (int i = 0; i < 2; i++)
#pragma unroll
        for (int j = 0; j < 4; j++) wmma::fill_fragment(acc[i][j], 0.0f);

    for (int kb = 0; kb < 128; kb += 32) {
        // A chunk 128x32: 1024 float4 over 256 threads, packed split on store
#pragma unroll
        for (int i = 0; i < 4; i++) {
            int idx = tid + i * 256;
            int m = idx >> 3, k4 = idx & 7;
            int gr = r0 + m;
            if (gr >= M) gr = r0;
            float4 v = *(const float4*)(A + (size_t)gr * 128 + kb + k4 * 4);
            unsigned h0, l0, h1, l1;
            split_pair(v.x, v.y, h0, l0);
            split_pair(v.z, v.w, h1, l1);
            *(uint2*)&sAh[m][k4 * 4] = make_uint2(h0, h1);
            *(uint2*)&sAl[m][k4 * 4] = make_uint2(l0, l1);
        }
        // W chunk 32x128
#pragma unroll
        for (int i = 0; i < 4; i++) {
            int idx = tid + i * 256;
            int k = idx >> 5, n4 = idx & 31;
            float4 v = *(const float4*)(W + (size_t)(kb + k) * 128 + n4 * 4);
            unsigned h0, l0, h1, l1;
            split_pair(v.x, v.y, h0, l0);
            split_pair(v.z, v.w, h1, l1);
            *(uint2*)&sWh[k][n4 * 4] = make_uint2(h0, h1);
            *(uint2*)&sWl[k][n4 * 4] = make_uint2(l0, l1);
        }
        __syncthreads();

#pragma unroll
        for (int ks = 0; ks < 2; ks++) {
            wmma::fragment<wmma::matrix_a, 16, 16, 16, __nv_bfloat16, wmma::row_major> ah[2], al[2];
#pragma unroll
            for (int im = 0; im < 2; im++) {
                wmma::load_matrix_sync(ah[im], &sAh[wm + im * 16][ks * 16], 40);
                wmma::load_matrix_sync(al[im], &sAl[wm + im * 16][ks * 16], 40);
            }
#pragma unroll
            for (int in = 0; in < 4; in++) {
                wmma::fragment<wmma::matrix_b, 16, 16, 16, __nv_bfloat16, wmma::row_major> bh, bl;
                wmma::load_matrix_sync(bh, &sWh[ks * 16][wn + in * 16], 136);
                wmma::load_matrix_sync(bl, &sWl[ks * 16][wn + in * 16], 136);
#pragma unroll
                for (int im = 0; im < 2; im++) {
                    wmma::mma_sync(acc[im][in], ah[im], bh, acc[im][in]);
                    wmma::mma_sync(acc[im][in], ah[im], bl, acc[im][in]);
                    wmma::mma_sync(acc[im][in], al[im], bh, acc[im][in]);
                }
            }
        }
        __syncthreads();
    }

    // Epilogue: alias the A-tile smem as per-warp fp32 scratch (16x16, ldm 20)
    float* scratch = (float*)&sAh[0][0] + wid * 320;   // 8 warps * 320 floats = 10KB

#pragma unroll
    for (int im = 0; im < 2; im++) {
#pragma unroll
        for (int in = 0; in < 4; in++) {
            wmma::store_matrix_sync(scratch, acc[im][in], 20, wmma::mem_row_major);
            __syncwarp();
            int row = lane >> 2;    // 0..7
            int c4 = lane & 3;      // 0..3
            int ncol = wn + in * 16 + c4 * 4;
            float4 bb = *(const float4*)(bias + ncol);
#pragma unroll
            for (int h = 0; h < 2; h++) {
                int r = row + h * 8;
                int gr = r0 + wm + im * 16 + r;
                if (gr < M) {
                    float4 v = *(float4*)&scratch[r * 20 + c4 * 4];
                    v.x += bb.x; v.y += bb.y; v.z += bb.z; v.w += bb.w;
                    if (RELU) {
                        v.x = fmaxf(v.x, 0.f); v.y = fmaxf(v.y, 0.f);
                        v.z = fmaxf(v.z, 0.f); v.w = fmaxf(v.w, 0.f);
                    }
                    *(float4*)(C + (size_t)gr * 128 + ncol) = v;
                }
            }
            __syncwarp();
        }
    }
}

// ---------------------------------------------------------------------------
// out[n, :] = log_softmax(H[n, :] @ Wl + bl)
// ---------------------------------------------------------------------------
__global__ void __launch_bounds__(256) classify_lsm(
    const float* __restrict__ H, const float* __restrict__ Wl,
    const float* __restrict__ bl, float* __restrict__ out, int M)
{
    __shared__ float sW[128 * NC];
    __shared__ float sb[NC];
    __shared__ float sh[32 * 129];
    __shared__ float sl[32 * NC];

    const int tid = threadIdx.x;
    const int r0 = blockIdx.x * 32;

    for (int i = tid; i < 128 * NC; i += 256) sW[i] = Wl[i];
    if (tid < NC) sb[tid] = bl[tid];
    for (int i = tid; i < 32 * 128; i += 256) {
        int row = i >> 7, col = i & 127;
        int gr = r0 + row;
        sh[row * 129 + col] = (gr < M) ? H[(size_t)gr * 128 + col] : 0.0f;
    }
    __syncthreads();

#pragma unroll
    for (int t = 0; t < 5; t++) {
        int idx = tid + t * 256;
        int row = idx / NC, col = idx % NC;
        float acc = sb[col];
#pragma unroll 8
        for (int k = 0; k < 128; k++)
            acc = fmaf(sh[row * 129 + k], sW[k * NC + col], acc);
        sl[row * NC + col] = acc;
    }
    __syncthreads();

    if (tid < 32) {
        int row = tid;
        int gr = r0 + row;
        if (gr < M) {
            float mx = -1e30f;
            for (int c = 0; c < NC; c++) mx = fmaxf(mx, sl[row * NC + c]);
            float sum = 0.0f;
            for (int c = 0; c < NC; c++) sum += expf(sl[row * NC + c] - mx);
            float lse = mx + logf(sum);
            for (int c = 0; c < NC; c++)
                out[(size_t)gr * NC + c] = sl[row * NC + c] - lse;
        }
    }
}

// ---------------------------------------------------------------------------
extern "C" void kernel_launch(void* const* d_in, const int* in_sizes, int n_in,
                              void* d_out, int out_size)
{
    const float* x    = (const float*)d_in[0];
    const int*   ei   = (const int*)d_in[1];      // int32 (JAX x64 disabled)
    const float* ea   = (const float*)d_in[2];
    const float* eps1 = (const float*)d_in[3];
    const float* We1  = (const float*)d_in[4];
    const float* be1  = (const float*)d_in[5];
    const float* W11  = (const float*)d_in[6];
    const float* b11  = (const float*)d_in[7];
    const float* W12  = (const float*)d_in[8];
    const float* b12  = (const float*)d_in[9];
    const float* eps2 = (const float*)d_in[10];
    const float* We2  = (const float*)d_in[11];
    const float* be2  = (const float*)d_in[12];
    const float* W21  = (const float*)d_in[13];
    const float* b21  = (const float*)d_in[14];
    const float* W22  = (const float*)d_in[15];
    const float* b22  = (const float*)d_in[16];
    const float* Wl   = (const float*)d_in[17];
    const float* bl   = (const float*)d_in[18];
    float* out = (float*)d_out;

    const int N = NN;
    const int E = in_sizes[2];

    float *A, *B, *C;
    int *deg, *excl, *btot, *off, *cur;
    int2 *se;
    cudaGetSymbolAddress((void**)&A, g_bufA);
    cudaGetSymbolAddress((void**)&B, g_bufB);
    cudaGetSymbolAddress((void**)&C, g_bufC);
    cudaGetSymbolAddress((void**)&deg, g_deg);
    cudaGetSymbolAddress((void**)&excl, g_excl);
    cudaGetSymbolAddress((void**)&btot, g_btot);
    cudaGetSymbolAddress((void**)&off, g_off);
    cudaGetSymbolAddress((void**)&cur, g_cur);
    cudaGetSymbolAddress((void**)&se, g_se);

    const int eb = (E + 255) / 256;
    const int nb = (N + 255) / 256;
    const int gemm_blocks = (N + 127) / 128;
    const int cls_blocks = (N + 31) / 32;
    const int agg_blocks = (N * 32 + 255) / 256;   // warp per node

    // ---- One-time counting sort of edges by dst ----
    zero_int<<<nb, 256>>>(deg, N);
    count_deg<<<eb, 256>>>(ei, deg, E);
    scan1<<<SCAN_NB, SCAN_B>>>(deg, excl, btot, N);
    scan2<<<1, 256>>>(btot, SCAN_NB);
    scan3<<<SCAN_NB, SCAN_B>>>(excl, btot, off, cur, N, E);
    scatter_edges<<<eb, 256>>>(ei, ea, cur, se, E);

    // ---- Layer 1 ----
    aggregate<<<agg_blocks, 256>>>((const float4*)x, se, off, eps1, We1, be1,
                                   (float4*)A, N);
    gemm_bf<true><<<gemm_blocks, 256>>>(A, W11, b11, B, N);
    gemm_bf<true><<<gemm_blocks, 256>>>(B, W12, b12, C, N);   // outer relu fused

    // ---- Layer 2 ----
    aggregate<<<agg_blocks, 256>>>((const float4*)C, se, off, eps2, We2, be2,
                                   (float4*)B, N);
    gemm_bf<true><<<gemm_blocks, 256>>>(B, W21, b21, A, N);
    gemm_bf<true><<<gemm_blocks, 256>>>(A, W22, b22, B, N);   // outer relu fused

    // ---- Classifier + log_softmax ----
    classify_lsm<<<cls_blocks, 256>>>(B, Wl, bl, out, N);
}